// round 16
// baseline (speedup 1.0000x reference)
#include <cuda_runtime.h>
#include <cuda_bf16.h>
#include <math.h>
#include <cstdint>

// ---------------- problem constants ----------------
#define BATCH 4
#define CCH   48
#define HW    4096
#define HID   96
#define NSET  32
#define HEADS 8
#define DHEAD 6
#define INTERC 24

typedef unsigned long long u64;
__device__ __forceinline__ u64 pk2(float lo, float hi){ u64 r; asm("mov.b64 %0,{%1,%2};":"=l"(r):"f"(lo),"f"(hi)); return r; }
__device__ __forceinline__ u64 dup2(float v){ return pk2(v, v); }
__device__ __forceinline__ u64 fma2_(u64 a, u64 b, u64 c){ u64 d; asm("fma.rn.f32x2 %0,%1,%2,%3;":"=l"(d):"l"(a),"l"(b),"l"(c)); return d; }

__device__ __forceinline__ void mma_bf16(float* d, const uint32_t* a, const uint32_t* b){
    asm volatile("mma.sync.aligned.m16n8k16.row.col.f32.bf16.bf16.f32 "
        "{%0,%1,%2,%3}, {%4,%5,%6,%7}, {%8,%9}, {%0,%1,%2,%3};"
        : "+f"(d[0]),"+f"(d[1]),"+f"(d[2]),"+f"(d[3])
        : "r"(a[0]),"r"(a[1]),"r"(a[2]),"r"(a[3]), "r"(b[0]),"r"(b[1]));
}

// ---------------- scratch layout ----------------
#define OFF_XN    0LL
#define OFF_T1    (OFF_XN   + (long long)BATCH*CCH*HW)
#define OFF_T2    (OFF_T1   + (long long)BATCH*HID*HW)
#define OFF_X1    (OFF_T2   + (long long)BATCH*HID*HW)
#define OFF_UF    (OFF_X1   + (long long)BATCH*HID*HW)
#define OFF_ATT   (OFF_UF   + (long long)BATCH*HID*HW)
#define OFF_QKVT  (OFF_ATT  + (long long)BATCH*NSET*HW)
#define OFF_QKV   (OFF_QKVT + (long long)BATCH*3*CCH*HW)
#define OFF_M     (OFF_QKV  + (long long)BATCH*3*CCH*HW)
#define OFF_GAP   (OFF_M    + (long long)BATCH*HID*HW)
#define OFF_ATTN  (OFF_GAP  + BATCH*CCH)
#define OFF_KWB   (OFF_ATTN + BATCH*HEADS*DHEAD*DHEAD)
#define SCRATCH_TOTAL (OFF_KWB + 24*160*32/2 + 64)

__device__ float g_scratch[SCRATCH_TOTAL];

// ---------------- merged kwb prep + gap ----------------
#define GAPB (BATCH * CCH)
__global__ void prepgap_k(const float* __restrict__ x,
                          const float* __restrict__ kw, const float* __restrict__ kb,
                          float* __restrict__ gap, __nv_bfloat16* __restrict__ kwb)
{
    if (blockIdx.x < GAPB) {
        int bc = blockIdx.x;
        const float* xb = x + (size_t)bc * HW;
        __shared__ float red[256];
        float s = 0.f;
        for (int i = threadIdx.x; i < HW; i += 256) s += xb[i];
        red[threadIdx.x] = s; __syncthreads();
        for (int st = 128; st; st >>= 1) {
            if (threadIdx.x < st) red[threadIdx.x] += red[threadIdx.x + st];
            __syncthreads();
        }
        if (threadIdx.x == 0) gap[bc] = red[0] * (1.f / HW);
        return;
    }
    int i = (blockIdx.x - GAPB) * 256 + threadIdx.x;
    if (i < 24 * 160 * 32) {
        int g = i / (160 * 32);
        int rem = i % (160 * 32);
        int row = rem >> 5, n = rem & 31;
        int c = row / 40, rr = row - c * 40;
        float v;
        if (rr < 36)       v = kw[(size_t)n * 3456 + g * 144 + c * 36 + rr];
        else if (rr == 36) v = kb[n * HID + g * 4 + c];
        else               v = 0.f;
        kwb[i] = __float2bfloat16_rn(v);
    }
}

// ---------------- LayerNorm (xn only, feeds attmix) ----------------
__global__ __launch_bounds__(256) void ln_k(const float* __restrict__ x,
        const float* __restrict__ n1w, const float* __restrict__ n1b,
        float* __restrict__ xn)
{
    __shared__ float S1[256], S2[256];
    int tid = threadIdx.x;
    int px = tid & 63, grp = tid >> 6;
    int pg = blockIdx.x * 64 + px;
    int b = pg >> 12, p = pg & 4095;
    const float* xb = x + (size_t)b * CCH * HW + p + (size_t)grp * 12 * HW;
    float v[12]; float s = 0.f, s2 = 0.f;
#pragma unroll
    for (int c = 0; c < 12; c++) { float t = xb[(size_t)c * HW]; v[c] = t; s += t; s2 += t * t; }
    S1[tid] = s; S2[tid] = s2;
    __syncthreads();
    float st  = S1[px] + S1[px + 64] + S1[px + 128] + S1[px + 192];
    float st2 = S2[px] + S2[px + 64] + S2[px + 128] + S2[px + 192];
    float mu = st * (1.f / CCH);
    float var = st2 * (1.f / CCH) - mu * mu;
    float r = rsqrtf(var + 1e-6f);
    float* xnb = xn + (size_t)b * CCH * HW + p + (size_t)grp * 12 * HW;
#pragma unroll
    for (int c = 0; c < 12; c++) {
        int cg = grp * 12 + c;
        xnb[(size_t)c * HW] = n1w[cg] * (v[c] - mu) * r + n1b[cg];
    }
}

// ---------------- fused2 warp MMA + inline LN + inline weight cvt, y=2 ----------------
__global__ __launch_bounds__(256) void fused3m_k(const float* __restrict__ x,
        const float* __restrict__ n1w, const float* __restrict__ n1b,
        const float* __restrict__ w1, const float* __restrict__ w2,
        float* __restrict__ t1, float* __restrict__ t2)
{
    __shared__ uint32_t A32[128 * 28];
    __shared__ uint32_t WB32[96 * 28];
    __shared__ float SS1[256], SS2[256];
    __shared__ float sw1[CCH], sb1[CCH];
    int tid = threadIdx.x, wid = tid >> 5, lane = tid & 31;
    int c0 = lane & 3, rq = lane >> 2;
    int y = blockIdx.y;
    int ob = y * 96;
    int pb = blockIdx.x * 128;
    int b = pb >> 12, pp0 = pb & 4095;
    int px = tid & 127, half = tid >> 7;
    int pp = pp0 + px;

    if (tid < CCH) { sw1[tid] = n1w[tid]; sb1[tid] = n1b[tid]; }
    const float* xb = x + (size_t)b * CCH * HW + pp;
    float v[24];
    float s = 0.f, s2 = 0.f;
#pragma unroll
    for (int w = 0; w < 12; w++) {
        int c = (half * 12 + w) * 2;
        float a0 = xb[(size_t)c * HW], a1 = xb[(size_t)(c + 1) * HW];
        v[2 * w] = a0; v[2 * w + 1] = a1;
        s += a0 + a1; s2 += a0 * a0 + a1 * a1;
    }
    SS1[tid] = s; SS2[tid] = s2;
    // inline weight conversion: this block's 96-channel slice
    for (int i = tid; i < 96 * 24; i += 256) {
        int o = i / 24, w = i % 24;
        int oc = ob + o;
        const float* wsrc = (oc < 96) ? (w1 + oc * 48) : (w2 + (oc - 96) * 48);
        __nv_bfloat162 bv;
        bv.x = __float2bfloat16_rn(wsrc[2 * w]);
        bv.y = __float2bfloat16_rn(wsrc[2 * w + 1]);
        WB32[o * 28 + w] = *(uint32_t*)&bv;
    }
    __syncthreads();
    {
        float st  = SS1[px] + SS1[px + 128];
        float st2 = SS2[px] + SS2[px + 128];
        float mu = st * (1.f / CCH);
        float var = st2 * (1.f / CCH) - mu * mu;
        float r = rsqrtf(var + 1e-6f);
#pragma unroll
        for (int w = 0; w < 12; w++) {
            int c = (half * 12 + w) * 2;
            __nv_bfloat162 bv;
            bv.x = __float2bfloat16_rn(sw1[c] * (v[2 * w] - mu) * r + sb1[c]);
            bv.y = __float2bfloat16_rn(sw1[c + 1] * (v[2 * w + 1] - mu) * r + sb1[c + 1]);
            A32[px * 28 + half * 12 + w] = *(uint32_t*)&bv;
        }
    }
    __syncthreads();

    int arow = wid * 16;
    uint32_t aF[3][4];
#pragma unroll
    for (int ks = 0; ks < 3; ks++) {
        aF[ks][0] = A32[(arow + rq) * 28 + ks * 8 + c0];
        aF[ks][1] = A32[(arow + rq + 8) * 28 + ks * 8 + c0];
        aF[ks][2] = A32[(arow + rq) * 28 + ks * 8 + c0 + 4];
        aF[ks][3] = A32[(arow + rq + 8) * 28 + ks * 8 + c0 + 4];
    }
#pragma unroll
    for (int nt = 0; nt < 12; nt++) {
        uint32_t bF[3][2];
        int rowb = (nt * 8 + rq) * 28;
#pragma unroll
        for (int ks = 0; ks < 3; ks++) { bF[ks][0] = WB32[rowb + ks * 8 + c0]; bF[ks][1] = WB32[rowb + ks * 8 + c0 + 4]; }
        float d[4] = {0.f, 0.f, 0.f, 0.f};
        mma_bf16(d, aF[0], bF[0]);
        mma_bf16(d, aF[1], bF[1]);
        mma_bf16(d, aF[2], bF[2]);
#pragma unroll
        for (int e = 0; e < 2; e++) {
            int oc = ob + nt * 8 + 2 * c0 + e;
            float* base = (oc < 96) ? t1 : t2;
            int oo = (oc < 96) ? oc : oc - 96;
            size_t o0 = ((size_t)b * HID + oo) * HW + pp0;
            base[o0 + arow + rq]     = d[e];
            base[o0 + arow + rq + 8] = d[e + 2];
        }
    }
}

// ---------------- qkv warp MMA + inline LN + inline weight cvt, y=2 ----------------
__global__ __launch_bounds__(256) void qkvm_k(const float* __restrict__ x,
        const float* __restrict__ n2w, const float* __restrict__ n2b,
        const float* __restrict__ qw, float* __restrict__ out)
{
    __shared__ uint32_t A32[128 * 28];
    __shared__ uint32_t WB32[72 * 28];
    __shared__ float SS1[256], SS2[256];
    __shared__ float sw1[CCH], sb1[CCH];
    int tid = threadIdx.x, wid = tid >> 5, lane = tid & 31;
    int c0 = lane & 3, rq = lane >> 2;
    int y = blockIdx.y;
    int ob = y * 72;
    int pb = blockIdx.x * 128;
    int b = pb >> 12, pp0 = pb & 4095;
    int px = tid & 127, half = tid >> 7;
    int pp = pp0 + px;

    if (tid < CCH) { sw1[tid] = n2w[tid]; sb1[tid] = n2b[tid]; }
    const float* xb = x + (size_t)b * CCH * HW + pp;
    float v[24];
    float s = 0.f, s2 = 0.f;
#pragma unroll
    for (int w = 0; w < 12; w++) {
        int c = (half * 12 + w) * 2;
        float a0 = xb[(size_t)c * HW], a1 = xb[(size_t)(c + 1) * HW];
        v[2 * w] = a0; v[2 * w + 1] = a1;
        s += a0 + a1; s2 += a0 * a0 + a1 * a1;
    }
    SS1[tid] = s; SS2[tid] = s2;
    for (int i = tid; i < 72 * 24; i += 256) {
        int o = i / 24, w = i % 24;
        const float* wsrc = qw + (ob + o) * 48;
        __nv_bfloat162 bv;
        bv.x = __float2bfloat16_rn(wsrc[2 * w]);
        bv.y = __float2bfloat16_rn(wsrc[2 * w + 1]);
        WB32[o * 28 + w] = *(uint32_t*)&bv;
    }
    __syncthreads();
    {
        float st  = SS1[px] + SS1[px + 128];
        float st2 = SS2[px] + SS2[px + 128];
        float mu = st * (1.f / CCH);
        float var = st2 * (1.f / CCH) - mu * mu;
        float r = rsqrtf(var + 1e-6f);
#pragma unroll
        for (int w = 0; w < 12; w++) {
            int c = (half * 12 + w) * 2;
            __nv_bfloat162 bv;
            bv.x = __float2bfloat16_rn(sw1[c] * (v[2 * w] - mu) * r + sb1[c]);
            bv.y = __float2bfloat16_rn(sw1[c + 1] * (v[2 * w + 1] - mu) * r + sb1[c + 1]);
            A32[px * 28 + half * 12 + w] = *(uint32_t*)&bv;
        }
    }
    __syncthreads();

    int arow = wid * 16;
    uint32_t aF[3][4];
#pragma unroll
    for (int ks = 0; ks < 3; ks++) {
        aF[ks][0] = A32[(arow + rq) * 28 + ks * 8 + c0];
        aF[ks][1] = A32[(arow + rq + 8) * 28 + ks * 8 + c0];
        aF[ks][2] = A32[(arow + rq) * 28 + ks * 8 + c0 + 4];
        aF[ks][3] = A32[(arow + rq + 8) * 28 + ks * 8 + c0 + 4];
    }
#pragma unroll
    for (int nt = 0; nt < 9; nt++) {
        uint32_t bF[3][2];
        int rowb = (nt * 8 + rq) * 28;
#pragma unroll
        for (int ks = 0; ks < 3; ks++) { bF[ks][0] = WB32[rowb + ks * 8 + c0]; bF[ks][1] = WB32[rowb + ks * 8 + c0 + 4]; }
        float d[4] = {0.f, 0.f, 0.f, 0.f};
        mma_bf16(d, aF[0], bF[0]);
        mma_bf16(d, aF[1], bF[1]);
        mma_bf16(d, aF[2], bF[2]);
#pragma unroll
        for (int e = 0; e < 2; e++) {
            int oc = ob + nt * 8 + 2 * c0 + e;
            size_t o0 = ((size_t)b * (3 * CCH) + oc) * HW + pp0;
            out[o0 + arow + rq]     = d[e];
            out[o0 + arow + rq + 8] = d[e + 2];
        }
    }
}

// ---------------- depthwise 3x3 for t1/t2 ----------------
__global__ void dw12_k(const float* __restrict__ t1, const float* __restrict__ kdw2,
                       const float* __restrict__ t2, const float* __restrict__ kc1b,
                       float* __restrict__ x1, float* __restrict__ uf)
{
    int gidx4 = (blockIdx.x * 256 + threadIdx.x);
    int p = (gidx4 * 4) & 4095;
    int plane = (gidx4 * 4) >> 12;
    int b = plane / 192, cg = plane % 192;
    const float* in; const float* wsrc; float* outp; int c;
    if (cg < 96) { in = t1; wsrc = kdw2; outp = x1; c = cg; }
    else         { in = t2; wsrc = kc1b; outp = uf; c = cg - 96; }
    int h = p >> 6, w0 = p & 63;
    const float* inp = in + ((size_t)b * 96 + c) * HW;
    const float* wc = wsrc + c * 9;
    float wk[9];
#pragma unroll
    for (int i = 0; i < 9; i++) wk[i] = __ldg(wc + i);
    float a[4] = {0.f, 0.f, 0.f, 0.f};
#pragma unroll
    for (int kh = 0; kh < 3; kh++) {
        int hh = h + kh - 1;
        if (hh < 0 || hh > 63) continue;
        const float* r = inp + hh * 64;
        float4 v14 = *(const float4*)(r + w0);
        float vm1 = (w0 > 0)  ? r[w0 - 1] : 0.f;
        float v5  = (w0 < 60) ? r[w0 + 4] : 0.f;
        float v[6] = {vm1, v14.x, v14.y, v14.z, v14.w, v5};
        float k0 = wk[kh * 3], k1 = wk[kh * 3 + 1], k2 = wk[kh * 3 + 2];
#pragma unroll
        for (int px = 0; px < 4; px++)
            a[px] += k0 * v[px] + k1 * v[px + 1] + k2 * v[px + 2];
    }
    ulonglong2 t; t.x = pk2(a[0], a[1]); t.y = pk2(a[2], a[3]);
    *(ulonglong2*)(outp + ((size_t)b * 96 + c) * HW + p) = t;
}

// ---------------- depthwise 3x3 for qkv ----------------
__global__ void dwq_k(const float* __restrict__ qkvt, const float* __restrict__ qkvw,
                      float* __restrict__ qkv)
{
    int gidx4 = (blockIdx.x * 256 + threadIdx.x);
    int p = (gidx4 * 4) & 4095;
    int plane = (gidx4 * 4) >> 12;
    int b = plane / 144, c = plane % 144;
    int h = p >> 6, w0 = p & 63;
    const float* inp = qkvt + ((size_t)b * 144 + c) * HW;
    const float* wc = qkvw + c * 9;
    float wk[9];
#pragma unroll
    for (int i = 0; i < 9; i++) wk[i] = __ldg(wc + i);
    float a[4] = {0.f, 0.f, 0.f, 0.f};
#pragma unroll
    for (int kh = 0; kh < 3; kh++) {
        int hh = h + kh - 1;
        if (hh < 0 || hh > 63) continue;
        const float* r = inp + hh * 64;
        float4 v14 = *(const float4*)(r + w0);
        float vm1 = (w0 > 0)  ? r[w0 - 1] : 0.f;
        float v5  = (w0 < 60) ? r[w0 + 4] : 0.f;
        float v[6] = {vm1, v14.x, v14.y, v14.z, v14.w, v5};
        float k0 = wk[kh * 3], k1 = wk[kh * 3 + 1], k2 = wk[kh * 3 + 2];
#pragma unroll
        for (int px = 0; px < 4; px++)
            a[px] += k0 * v[px] + k1 * v[px + 1] + k2 * v[px + 2];
    }
    ulonglong2 t; t.x = pk2(a[0], a[1]); t.y = pk2(a[2], a[3]);
    *(ulonglong2*)(qkv + ((size_t)b * 144 + c) * HW + p) = t;
}

// ---------------- attmix ----------------
__global__ __launch_bounds__(128) void attmix_k(const float* __restrict__ xn,
        const float* __restrict__ wA, const float* __restrict__ bA,
        const float* __restrict__ wB, const float* __restrict__ bB,
        const float* __restrict__ gam,
        const float* __restrict__ c211w, const float* __restrict__ c211b,
        float* __restrict__ att)
{
    __shared__ float swA[INTERC * 18], sbA[INTERC], swB[NSET * 12], sbB[NSET], sgam[NSET];
    __shared__ float sw3[NSET * CCH], sb3[NSET];
    __shared__ float scen[64 * 48];
    __shared__ float sav[64 * 24];
    int tid = threadIdx.x;
    for (int i = tid; i < INTERC * 18; i += 128) swA[i] = wA[i];
    if (tid < INTERC) sbA[tid] = bA[tid];
    for (int i = tid; i < NSET * 12; i += 128) swB[i] = wB[i];
    if (tid < NSET) { sbB[tid] = bB[tid]; sgam[tid] = gam[tid]; sb3[tid] = c211b[tid]; }
    for (int i = tid; i < NSET * CCH; i += 128) sw3[i] = c211w[i];
    __syncthreads();
    int px = tid & 63, half = tid >> 6;
    int pg = blockIdx.x * 64 + px;
    int b = pg >> 12, p = pg & 4095;
    int h = p >> 6, w = p & 63;
    const float* xb = xn + (size_t)b * CCH * HW;
#pragma unroll
    for (int oo = 0; oo < 12; oo++) {
        int o = half * 12 + oo;
        float acc = sbA[o];
#pragma unroll
        for (int t = 0; t < 2; t++) {
            int c = o * 2 + t;
            const float* ch = xb + (size_t)c * HW;
            float cen = 0.f;
#pragma unroll
            for (int kk = 0; kk < 9; kk++) {
                int hh = h + kk / 3 - 1, ww = w + kk % 3 - 1;
                if (hh >= 0 && hh < 64 && ww >= 0 && ww < 64) {
                    float vv = ch[hh * 64 + ww];
                    acc += swA[o * 18 + t * 9 + kk] * vv;
                    if (kk == 4) cen = vv;
                }
            }
            scen[px * 48 + c] = cen;
        }
        sav[px * 24 + o] = acc;
    }
    __syncthreads();
    float sg[12];
#pragma unroll
    for (int i = 0; i < 12; i++) sg[i] = sav[px * 24 + i] * sav[px * 24 + 12 + i];
#pragma unroll
    for (int nn = 0; nn < 16; nn++) {
        int n = half * 16 + nn;
        float s = sbB[n];
#pragma unroll
        for (int i = 0; i < 12; i++) s += swB[n * 12 + i] * sg[i];
        float c2 = sb3[n];
#pragma unroll
        for (int c = 0; c < 48; c++) c2 += sw3[n * 48 + c] * scen[px * 48 + c];
        att[((size_t)b * NSET + n) * HW + p] = sgam[n] * s + c2;
    }
}

// ================= KBA core via warp MMA, y-split x4 =================
#define KT_A 0
#define KT_B 18432
#define KT_P 41472
#define KT_TOTAL 61952

__global__ __launch_bounds__(256) void kba_mma_k(
        const float* __restrict__ uf, const float* __restrict__ att,
        const __nv_bfloat16* __restrict__ kwb, const float* __restrict__ ga1,
        const float* __restrict__ x1, float* __restrict__ mout)
{
    extern __shared__ __align__(16) char smraw[];
    uint32_t* A32 = (uint32_t*)(smraw + KT_A);
    uint32_t* B32 = (uint32_t*)(smraw + KT_B);
    float*    P   = (float*)(smraw + KT_P);

    int tid = threadIdx.x, wid = tid >> 5, lane = tid & 31;
    int c0 = lane & 3, rq = lane >> 2;
    int pb = blockIdx.x * 128;
    int b = pb >> 12, pp0 = pb & 4095;
    int g0 = blockIdx.y * 6;

    int px = tid & 127, half = tid >> 7;
    int pp = pp0 + px;
    int h = pp >> 6, w = pp & 63;

    {
        const float* attb = att + (size_t)b * NSET * HW + pp;
#pragma unroll
        for (int q = 0; q < 8; q++) {
            int n = (half * 8 + q) * 2;
            __nv_bfloat162 v;
            v.x = __float2bfloat16_rn(attb[(size_t)n * HW]);
            v.y = __float2bfloat16_rn(attb[(size_t)(n + 1) * HW]);
            A32[px * 36 + half * 8 + q] = *(uint32_t*)&v;
        }
    }
    int offs[9]; bool val[9];
#pragma unroll
    for (int kk = 0; kk < 9; kk++) {
        int dh = kk / 3 - 1, dw = kk % 3 - 1;
        int hh = h + dh, ww = w + dw;
        val[kk] = (hh >= 0 && hh < 64 && ww >= 0 && ww < 64);
        offs[kk] = hh * 64 + ww;
    }
    __syncthreads();

    int arow = 16 * wid + rq;
    uint32_t aF[2][4];
#pragma unroll
    for (int ks = 0; ks < 2; ks++) {
        int base = ks * 8;
        aF[ks][0] = A32[arow * 36 + base + c0];
        aF[ks][1] = A32[(arow + 8) * 36 + base + c0];
        aF[ks][2] = A32[arow * 36 + base + c0 + 4];
        aF[ks][3] = A32[(arow + 8) * 36 + base + c0 + 4];
    }

    for (int gi = 0; gi < 6; gi++) {
        int g = g0 + gi;
        __syncthreads();
        const uint32_t* kwb32 = (const uint32_t*)(kwb + (size_t)g * 160 * 32);
        for (int i = tid; i < 2560; i += 256) {
            int row = i >> 4, np = i & 15;
            B32[row * 36 + np] = kwb32[i];
        }
        const float* ufg = uf + ((size_t)b * HID + g * 4) * HW;
#pragma unroll
        for (int jj = 0; jj < 18; jj++) {
            int j = half * 18 + jj;
            int ci = j / 9, kk = j % 9;
            P[px * 40 + j] = val[kk] ? ufg[(size_t)ci * HW + offs[kk]] : 0.f;
        }
        __syncthreads();

#pragma unroll
        for (int cc = 0; cc < 4; cc++) {
            uint32_t bF[5][2][2];
            int nb = cc * 40;
#pragma unroll
            for (int t = 0; t < 5; t++) {
                int rowb = (nb + t * 8 + rq) * 36;
#pragma unroll
                for (int ks = 0; ks < 2; ks++) {
                    bF[t][ks][0] = B32[rowb + ks * 8 + c0];
                    bF[t][ks][1] = B32[rowb + ks * 8 + c0 + 4];
                }
            }
            float d[5][4];
#pragma unroll
            for (int t = 0; t < 5; t++) { d[t][0]=0.f; d[t][1]=0.f; d[t][2]=0.f; d[t][3]=0.f; }
#pragma unroll
            for (int t = 0; t < 5; t++) {
                mma_bf16(d[t], aF[0], bF[t][0]);
                mma_bf16(d[t], aF[1], bF[t][1]);
            }
            int rlo = 16 * wid + rq, rhi = rlo + 8;
            float s0 = 0.f, s1 = 0.f;
#pragma unroll
            for (int t = 0; t < 5; t++) {
                int j0 = t * 8 + 2 * c0, j1 = j0 + 1;
                float w00, w01, w10, w11;
                if (j0 < 36)      { w00 = P[rlo * 40 + j0]; w10 = P[rhi * 40 + j0]; }
                else if (j0 == 36){ w00 = 1.f; w10 = 1.f; }
                else              { w00 = 0.f; w10 = 0.f; }
                if (j1 < 36)      { w01 = P[rlo * 40 + j1]; w11 = P[rhi * 40 + j1]; }
                else              { w01 = 0.f; w11 = 0.f; }
                s0 += d[t][0] * w00 + d[t][1] * w01;
                s1 += d[t][2] * w10 + d[t][3] * w11;
            }
            s0 += __shfl_xor_sync(0xffffffffu, s0, 1);
            s0 += __shfl_xor_sync(0xffffffffu, s0, 2);
            s1 += __shfl_xor_sync(0xffffffffu, s1, 1);
            s1 += __shfl_xor_sync(0xffffffffu, s1, 2);
            if (c0 == 0) {
                int ch = g * 4 + cc;
                float ga = ga1[ch];
                float cen0 = P[rlo * 40 + cc * 9 + 4];
                float cen1 = P[rhi * 40 + cc * 9 + 4];
                float x2a = s0 * ga + cen0;
                float x2b = s1 * ga + cen1;
                size_t xlo = ((size_t)b * HID + ch) * HW + pp0 + rlo;
                size_t xhi = xlo + 8;
                float v0 = x1[xlo], v1 = x1[xhi];
                mout[xlo] = 0.5f * v0 * (1.f + erff(v0 * 0.70710678118654752f)) * x2a;
                mout[xhi] = 0.5f * v1 * (1.f + erff(v1 * 0.70710678118654752f)) * x2b;
            }
        }
    }
}

// ---------------- MDTA: fused norms + 6x6 attention + softmax ----------------
__global__ __launch_bounds__(256) void attn_k(const float* __restrict__ qkv,
        const float* __restrict__ temp, float* __restrict__ attn)
{
    int bh = blockIdx.x; int b = bh >> 3, h = bh & 7;
    int warp = threadIdx.x >> 5, lane = threadIdx.x & 31;
    __shared__ float S[36], NQ[6], NK[6];
    const float* qb = qkv + ((size_t)b * 3 * CCH + h * DHEAD) * HW;
    const float* kb = qkv + ((size_t)b * 3 * CCH + CCH + h * DHEAD) * HW;
    for (int pi = warp; pi < 48; pi += 8) {
        const float* pa; const float* pb;
        if (pi < 36)      { pa = qb + (size_t)(pi / 6) * HW; pb = kb + (size_t)(pi % 6) * HW; }
        else if (pi < 42) { pa = qb + (size_t)(pi - 36) * HW; pb = pa; }
        else              { pa = kb + (size_t)(pi - 42) * HW; pb = pa; }
        float s = 0.f;
        for (int t = lane * 4; t < HW; t += 128) {
            float4 va = *(const float4*)(pa + t);
            float4 vb = *(const float4*)(pb + t);
            s += va.x * vb.x + va.y * vb.y + va.z * vb.z + va.w * vb.w;
        }
#pragma unroll
        for (int off = 16; off; off >>= 1) s += __shfl_down_sync(0xffffffffu, s, off);
        if (lane == 0) {
            if (pi < 36) S[pi] = s;
            else if (pi < 42) NQ[pi - 36] = sqrtf(s);
            else NK[pi - 42] = sqrtf(s);
        }
    }
    __syncthreads();
    if (threadIdx.x < 6) {
        int i = threadIdx.x;
        float nq = fmaxf(NQ[i], 1e-12f);
        float tv = temp[h];
        float row[6]; float mx = -1e30f;
#pragma unroll
        for (int j = 0; j < 6; j++) {
            float nk = fmaxf(NK[j], 1e-12f);
            row[j] = tv * S[i * 6 + j] / (nq * nk);
            mx = fmaxf(mx, row[j]);
        }
        float sum = 0.f;
#pragma unroll
        for (int j = 0; j < 6; j++) { row[j] = expf(row[j] - mx); sum += row[j]; }
        float inv = 1.f / sum;
#pragma unroll
        for (int j = 0; j < 6; j++)
            attn[((size_t)(b * 8 + h) * 6 + i) * 6 + j] = row[j] * inv;
    }
}

// ---------------- MDTA: fused (attn @ v) + mproj ----------------
__global__ __launch_bounds__(128) void mdta_k(const float* __restrict__ qkv,
        const float* __restrict__ attn, const float* __restrict__ mproj,
        float* __restrict__ out)
{
    __shared__ float scoef[288];
    __shared__ u64 ws2[4 * CCH];
    int tid = threadIdx.x;
    int o0 = blockIdx.y * 4;
    int p4 = (blockIdx.x * 128 + tid) * 4;
    int b = p4 >> 12, pp = p4 & 4095;
    int bblk = (blockIdx.x * 512) >> 12;
    for (int i = tid; i < 288; i += 128) scoef[i] = attn[bblk * 288 + i];
    for (int i = tid; i < 4 * CCH; i += 128)
        ws2[i] = dup2(mproj[(o0 + i / CCH) * CCH + i % CCH]);
    __syncthreads();
    u64 acc[4][2];
#pragma unroll
    for (int o = 0; o < 4; o++) { acc[o][0] = 0ULL; acc[o][1] = 0ULL; }
    const float* vb = qkv + ((size_t)b * 3 * CCH + 2 * CCH) * HW + pp;
#pragma unroll
    for (int h = 0; h < 8; h++) {
        u64 v[6][2];
#pragma unroll
        for (int j = 0; j < 6; j++) {
            ulonglong2 t = *(const ulonglong2*)(vb + (size_t)(h * 6 + j) * HW);
            v[j][0] = t.x; v[j][1] = t.y;
        }
#pragma unroll
        for (int i = 0; i < 6; i++) {
            int c = h * 6 + i;
            u64 md0 = 0ULL, md1 = 0ULL;
#pragma unroll
            for (int j = 0; j < 6; j++) {
                u64 cf = dup2(scoef[c * 6 + j]);
                md0 = fma2_(cf, v[j][0], md0);
                md1 = fma2_(cf, v[j][1], md1);
            }
#pragma unroll
            for (int o = 0; o < 4; o++) {
                u64 wv = ws2[o * CCH + c];
                acc[o][0] = fma2_(wv, md0, acc[o][0]);
                acc[o][1] = fma2_(wv, md1, acc[o][1]);
            }
        }
    }
    float* outb = out + ((size_t)b * CCH + o0) * HW + pp;
#pragma unroll
    for (int o = 0; o < 4; o++) {
        ulonglong2 t; t.x = acc[o][0]; t.y = acc[o][1];
        *(ulonglong2*)(outb + (size_t)o * HW) = t;
    }
}

// ---------------- final via warp MMA ----------------
__global__ __launch_bounds__(256) void finalm_k(const float* __restrict__ x,
        const float* __restrict__ m, const float* __restrict__ mdta,
        const float* __restrict__ kproj, const float* __restrict__ gap,
        const float* __restrict__ ca1w, const float* __restrict__ ca1b,
        const float* __restrict__ ca2w, const float* __restrict__ ca2b,
        float* __restrict__ out)
{
    __shared__ uint32_t A32[128 * 52];
    __shared__ uint32_t WB32[48 * 52];
    __shared__ float sca1[48], sca2[48];
    int tid = threadIdx.x, wid = tid >> 5, lane = tid & 31;
    int c0 = lane & 3, rq = lane >> 2;
    int pb = blockIdx.x * 128;
    int b = pb >> 12, pp0 = pb & 4095;
    int px = tid & 127, half = tid >> 7;
    int pp = pp0 + px;

    const float* mb = m + (size_t)b * HID * HW + pp;
#pragma unroll
    for (int w = 0; w < 24; w++) {
        int c = (half * 24 + w) * 2;
        __nv_bfloat162 bv;
        bv.x = __float2bfloat16_rn(mb[(size_t)c * HW]);
        bv.y = __float2bfloat16_rn(mb[(size_t)(c + 1) * HW]);
        A32[px * 52 + half * 24 + w] = *(uint32_t*)&bv;
    }
    for (int i = tid; i < 48 * 48; i += 256) {
        int o = i / 48, w = i % 48;
        __nv_bfloat162 bv;
        bv.x = __float2bfloat16_rn(kproj[o * HID + 2 * w]);
        bv.y = __float2bfloat16_rn(kproj[o * HID + 2 * w + 1]);
        WB32[o * 52 + w] = *(uint32_t*)&bv;
    }
    if (tid < 48) {
        float s1 = ca1b[tid], s2 = ca2b[tid];
        for (int c = 0; c < CCH; c++) {
            float g = gap[b * CCH + c];
            s1 += ca1w[tid * CCH + c] * g;
            s2 += ca2w[tid * CCH + c] * g;
        }
        sca1[tid] = s1; sca2[tid] = s2;
    }
    __syncthreads();

    int arow = wid * 16;
    uint32_t aF[6][4];
#pragma unroll
    for (int ks = 0; ks < 6; ks++) {
        aF[ks][0] = A32[(arow + rq) * 52 + ks * 8 + c0];
        aF[ks][1] = A32[(arow + rq + 8) * 52 + ks * 8 + c0];
        aF[ks][2] = A32[(arow + rq) * 52 + ks * 8 + c0 + 4];
        aF[ks][3] = A32[(arow + rq + 8) * 52 + ks * 8 + c0 + 4];
    }
#pragma unroll
    for (int nt = 0; nt < 6; nt++) {
        uint32_t bF[6][2];
        int rowb = (nt * 8 + rq) * 52;
#pragma unroll
        for (int ks = 0; ks < 6; ks++) { bF[ks][0] = WB32[rowb + ks * 8 + c0]; bF[ks][1] = WB32[rowb + ks * 8 + c0 + 4]; }
        float d[4] = {0.f, 0.f, 0.f, 0.f};
#pragma unroll
        for (int ks = 0; ks < 6; ks++) mma_bf16(d, aF[ks], bF[ks]);
#pragma unroll
        for (int e = 0; e < 2; e++) {
            int oc = nt * 8 + 2 * c0 + e;
            float a1 = sca1[oc], a2 = sca2[oc];
            size_t o0 = ((size_t)b * CCH + oc) * HW + pp0;
            size_t i0 = o0 + arow + rq, i1 = i0 + 8;
            out[i0] = x[i0] + a1 * d[e]     + a2 * mdta[i0];
            out[i1] = x[i1] + a1 * d[e + 2] + a2 * mdta[i1];
        }
    }
}

// ---------------- host launcher ----------------
extern "C" void kernel_launch(void* const* d_in, const int* in_sizes, int n_in,
                              void* d_out, int out_size)
{
    const float* x       = (const float*)d_in[0];
    const float* n1w     = (const float*)d_in[1];
    const float* n1b     = (const float*)d_in[2];
    const float* n2w     = (const float*)d_in[3];
    const float* n2b     = (const float*)d_in[4];
    const float* kdw1    = (const float*)d_in[5];
    const float* kdw2    = (const float*)d_in[6];
    const float* kc1a    = (const float*)d_in[7];
    const float* kc1b    = (const float*)d_in[8];
    const float* kproj   = (const float*)d_in[9];
    const float* c2a_w   = (const float*)d_in[10];
    const float* c2a_b   = (const float*)d_in[11];
    const float* c2b_w   = (const float*)d_in[12];
    const float* c2b_b   = (const float*)d_in[13];
    const float* c211_w  = (const float*)d_in[14];
    const float* c211_b  = (const float*)d_in[15];
    const float* kw      = (const float*)d_in[16];
    const float* kb      = (const float*)d_in[17];
    const float* attg    = (const float*)d_in[18];
    const float* ga1     = (const float*)d_in[19];
    const float* temp    = (const float*)d_in[20];
    const float* qkv_w   = (const float*)d_in[21];
    const float* qkv_dww = (const float*)d_in[22];
    const float* mproj_w = (const float*)d_in[23];
    const float* ca1_w   = (const float*)d_in[24];
    const float* ca1_b   = (const float*)d_in[25];
    const float* ca2_w   = (const float*)d_in[26];
    const float* ca2_b   = (const float*)d_in[27];
    float* out = (float*)d_out;

    float* S = nullptr;
    cudaGetSymbolAddress((void**)&S, g_scratch);
    float* xn   = S + OFF_XN;
    float* t1   = S + OFF_T1;
    float* t2   = S + OFF_T2;
    float* x1   = S + OFF_X1;
    float* uf   = S + OFF_UF;
    float* att  = S + OFF_ATT;
    float* qkvt = S + OFF_QKVT;
    float* qkv  = S + OFF_QKV;
    float* m    = S + OFF_M;
    float* gap  = S + OFF_GAP;
    float* attn = S + OFF_ATTN;
    __nv_bfloat16* kwb = (__nv_bfloat16*)(S + OFF_KWB);
    float* mdta = qkvt;                     // reuse

    const int PIX = BATCH * HW;             // 16384
    const int XB4 = PIX / 512;              // 32

    static cudaStream_t sB = nullptr, sC = nullptr;
    static cudaEvent_t evRoot = nullptr, evP = nullptr, evB = nullptr, evC = nullptr;
    if (sB == nullptr) {
        cudaStreamCreateWithFlags(&sB, cudaStreamNonBlocking);
        cudaStreamCreateWithFlags(&sC, cudaStreamNonBlocking);
        cudaEventCreateWithFlags(&evRoot, cudaEventDisableTiming);
        cudaEventCreateWithFlags(&evP, cudaEventDisableTiming);
        cudaEventCreateWithFlags(&evB, cudaEventDisableTiming);
        cudaEventCreateWithFlags(&evC, cudaEventDisableTiming);
        cudaFuncSetAttribute(kba_mma_k, cudaFuncAttributeMaxDynamicSharedMemorySize, KT_TOTAL);
    }

    cudaEventRecord(evRoot, 0);
    cudaStreamWaitEvent(sC, evRoot, 0);
    cudaStreamWaitEvent(sB, evRoot, 0);

    // ---- stream C: ln(xn) -> attmix ----
    ln_k<<<PIX / 64, 256, 0, sC>>>(x, n1w, n1b, xn);
    attmix_k<<<PIX / 64, 128, 0, sC>>>(xn, c2a_w, c2a_b, c2b_w, c2b_b, attg,
                                       c211_w, c211_b, att);
    cudaEventRecord(evC, sC);

    // ---- stream B: kwb+gap prep, then MDTA chain ----
    const int PREP_N = 24 * 160 * 32;
    prepgap_k<<<GAPB + (PREP_N + 255) / 256, 256, 0, sB>>>(x, kw, kb, gap, kwb);
    cudaEventRecord(evP, sB);
    qkvm_k<<<dim3(PIX / 128, 2), 256, 0, sB>>>(x, n2w, n2b, qkv_w, qkvt);
    dwq_k<<<BATCH * 144 * HW / 1024, 256, 0, sB>>>(qkvt, qkv_dww, qkv);
    attn_k<<<BATCH * HEADS, 256, 0, sB>>>(qkv, temp, attn);
    mdta_k<<<dim3(XB4, 12), 128, 0, sB>>>(qkv, attn, mproj_w, mdta);
    cudaEventRecord(evB, sB);

    // ---- main: KBA critical path (starts immediately) ----
    fused3m_k<<<dim3(PIX / 128, 2), 256>>>(x, n1w, n1b, kdw1, kc1a, t1, t2);
    dw12_k<<<BATCH * 192 * HW / 1024, 256>>>(t1, kdw2, t2, kc1b, x1, uf);
    cudaStreamWaitEvent(0, evC, 0);
    cudaStreamWaitEvent(0, evP, 0);
    kba_mma_k<<<dim3(PIX / 128, 4), 256, KT_TOTAL>>>(uf, att, kwb, ga1, x1, m);
    cudaStreamWaitEvent(0, evB, 0);
    finalm_k<<<PIX / 128, 256>>>(x, m, mdta, kproj, gap,
                                 ca1_w, ca1_b, ca2_w, ca2_b, out);
}

// round 17
// speedup vs baseline: 1.4110x; 1.4110x over previous
#include <cuda_runtime.h>
#include <cuda_bf16.h>
#include <math.h>
#include <cstdint>

// ---------------- problem constants ----------------
#define BATCH 4
#define CCH   48
#define HW    4096
#define HID   96
#define NSET  32
#define HEADS 8
#define DHEAD 6
#define INTERC 24

typedef unsigned long long u64;
__device__ __forceinline__ u64 pk2(float lo, float hi){ u64 r; asm("mov.b64 %0,{%1,%2};":"=l"(r):"f"(lo),"f"(hi)); return r; }
__device__ __forceinline__ u64 dup2(float v){ return pk2(v, v); }
__device__ __forceinline__ u64 fma2_(u64 a, u64 b, u64 c){ u64 d; asm("fma.rn.f32x2 %0,%1,%2,%3;":"=l"(d):"l"(a),"l"(b),"l"(c)); return d; }

__device__ __forceinline__ void mma_bf16(float* d, const uint32_t* a, const uint32_t* b){
    asm volatile("mma.sync.aligned.m16n8k16.row.col.f32.bf16.bf16.f32 "
        "{%0,%1,%2,%3}, {%4,%5,%6,%7}, {%8,%9}, {%0,%1,%2,%3};"
        : "+f"(d[0]),"+f"(d[1]),"+f"(d[2]),"+f"(d[3])
        : "r"(a[0]),"r"(a[1]),"r"(a[2]),"r"(a[3]), "r"(b[0]),"r"(b[1]));
}

// ---------------- scratch layout ----------------
#define OFF_XN    0LL
#define OFF_T1    (OFF_XN   + (long long)BATCH*CCH*HW)
#define OFF_T2    (OFF_T1   + (long long)BATCH*HID*HW)
#define OFF_X1    (OFF_T2   + (long long)BATCH*HID*HW)
#define OFF_UF    (OFF_X1   + (long long)BATCH*HID*HW)
#define OFF_ATT   (OFF_UF   + (long long)BATCH*HID*HW)
#define OFF_QKVT  (OFF_ATT  + (long long)BATCH*NSET*HW)
#define OFF_QKV   (OFF_QKVT + (long long)BATCH*3*CCH*HW)
#define OFF_M     (OFF_QKV  + (long long)BATCH*3*CCH*HW)
#define OFF_GAP   (OFF_M    + (long long)BATCH*HID*HW)
#define OFF_ATTN  (OFF_GAP  + BATCH*CCH)
#define OFF_KWB   (OFF_ATTN + BATCH*HEADS*DHEAD*DHEAD)
#define OFF_WB    (OFF_KWB + 24*160*32/2 + 64)
#define OFF_WQ    (OFF_WB  + 192*48/2 + 32)
#define SCRATCH_TOTAL (OFF_WQ + 144*48/2 + 32)

__device__ float g_scratch[SCRATCH_TOTAL];

// ---------------- merged prep + gap ----------------
#define GAPB (BATCH * CCH)
__global__ void prepgap_k(const float* __restrict__ x,
                          const float* __restrict__ kw, const float* __restrict__ kb,
                          const float* __restrict__ w1, const float* __restrict__ w2,
                          const float* __restrict__ qw,
                          float* __restrict__ gap,
                          __nv_bfloat16* __restrict__ kwb,
                          __nv_bfloat16* __restrict__ wb, __nv_bfloat16* __restrict__ wq)
{
    if (blockIdx.x < GAPB) {
        int bc = blockIdx.x;
        const float* xb = x + (size_t)bc * HW;
        __shared__ float red[256];
        float s = 0.f;
        for (int i = threadIdx.x; i < HW; i += 256) s += xb[i];
        red[threadIdx.x] = s; __syncthreads();
        for (int st = 128; st; st >>= 1) {
            if (threadIdx.x < st) red[threadIdx.x] += red[threadIdx.x + st];
            __syncthreads();
        }
        if (threadIdx.x == 0) gap[bc] = red[0] * (1.f / HW);
        return;
    }
    int i = (blockIdx.x - GAPB) * 256 + threadIdx.x;
    if (i < 24 * 160 * 32) {
        int g = i / (160 * 32);
        int rem = i % (160 * 32);
        int row = rem >> 5, n = rem & 31;
        int c = row / 40, rr = row - c * 40;
        float v;
        if (rr < 36)       v = kw[(size_t)n * 3456 + g * 144 + c * 36 + rr];
        else if (rr == 36) v = kb[n * HID + g * 4 + c];
        else               v = 0.f;
        kwb[i] = __float2bfloat16_rn(v);
    } else if (i < 24 * 160 * 32 + 192 * 48) {
        int j = i - 24 * 160 * 32;
        int o = j / 48, c = j % 48;
        float v = (o < 96) ? w1[o * 48 + c] : w2[(o - 96) * 48 + c];
        wb[j] = __float2bfloat16_rn(v);
    } else if (i < 24 * 160 * 32 + 192 * 48 + 144 * 48) {
        int j = i - 24 * 160 * 32 - 192 * 48;
        wq[j] = __float2bfloat16_rn(qw[j]);
    }
}

// ---------------- LayerNorm (xn only, feeds attmix) ----------------
__global__ __launch_bounds__(256) void ln_k(const float* __restrict__ x,
        const float* __restrict__ n1w, const float* __restrict__ n1b,
        float* __restrict__ xn)
{
    __shared__ float S1[256], S2[256];
    int tid = threadIdx.x;
    int px = tid & 63, grp = tid >> 6;
    int pg = blockIdx.x * 64 + px;
    int b = pg >> 12, p = pg & 4095;
    const float* xb = x + (size_t)b * CCH * HW + p + (size_t)grp * 12 * HW;
    float v[12]; float s = 0.f, s2 = 0.f;
#pragma unroll
    for (int c = 0; c < 12; c++) { float t = xb[(size_t)c * HW]; v[c] = t; s += t; s2 += t * t; }
    S1[tid] = s; S2[tid] = s2;
    __syncthreads();
    float st  = S1[px] + S1[px + 64] + S1[px + 128] + S1[px + 192];
    float st2 = S2[px] + S2[px + 64] + S2[px + 128] + S2[px + 192];
    float mu = st * (1.f / CCH);
    float var = st2 * (1.f / CCH) - mu * mu;
    float r = rsqrtf(var + 1e-6f);
    float* xnb = xn + (size_t)b * CCH * HW + p + (size_t)grp * 12 * HW;
#pragma unroll
    for (int c = 0; c < 12; c++) {
        int cg = grp * 12 + c;
        xnb[(size_t)c * HW] = n1w[cg] * (v[c] - mu) * r + n1b[cg];
    }
}

// ---------------- fused2 via warp MMA with inline LN: x -> t1(96), t2(96) ----------------
__global__ __launch_bounds__(256) void fused3m_k(const float* __restrict__ x,
        const float* __restrict__ n1w, const float* __restrict__ n1b,
        const __nv_bfloat16* __restrict__ wb,
        float* __restrict__ t1, float* __restrict__ t2)
{
    __shared__ uint32_t A32[128 * 28];
    __shared__ uint32_t WB32[96 * 28];
    __shared__ float SS1[256], SS2[256];
    __shared__ float sw1[CCH], sb1[CCH];
    int tid = threadIdx.x, wid = tid >> 5, lane = tid & 31;
    int c0 = lane & 3, rq = lane >> 2;
    int y = blockIdx.y;
    int ob = y * 96;
    int pb = blockIdx.x * 128;
    int b = pb >> 12, pp0 = pb & 4095;
    int px = tid & 127, half = tid >> 7;
    int pp = pp0 + px;

    if (tid < CCH) { sw1[tid] = n1w[tid]; sb1[tid] = n1b[tid]; }
    const float* xb = x + (size_t)b * CCH * HW + pp;
    float v[24];
    float s = 0.f, s2 = 0.f;
#pragma unroll
    for (int w = 0; w < 12; w++) {
        int c = (half * 12 + w) * 2;
        float a0 = xb[(size_t)c * HW], a1 = xb[(size_t)(c + 1) * HW];
        v[2 * w] = a0; v[2 * w + 1] = a1;
        s += a0 + a1; s2 += a0 * a0 + a1 * a1;
    }
    SS1[tid] = s; SS2[tid] = s2;
    const uint32_t* wbg = (const uint32_t*)wb;
    for (int i = tid; i < 96 * 24; i += 256) {
        int o = i / 24, w = i % 24;
        WB32[o * 28 + w] = wbg[(ob + o) * 24 + w];
    }
    __syncthreads();
    {
        float st  = SS1[px] + SS1[px + 128];
        float st2 = SS2[px] + SS2[px + 128];
        float mu = st * (1.f / CCH);
        float var = st2 * (1.f / CCH) - mu * mu;
        float r = rsqrtf(var + 1e-6f);
#pragma unroll
        for (int w = 0; w < 12; w++) {
            int c = (half * 12 + w) * 2;
            __nv_bfloat162 bv;
            bv.x = __float2bfloat16_rn(sw1[c] * (v[2 * w] - mu) * r + sb1[c]);
            bv.y = __float2bfloat16_rn(sw1[c + 1] * (v[2 * w + 1] - mu) * r + sb1[c + 1]);
            A32[px * 28 + half * 12 + w] = *(uint32_t*)&bv;
        }
    }
    __syncthreads();

    int arow = wid * 16;
    uint32_t aF[3][4];
#pragma unroll
    for (int ks = 0; ks < 3; ks++) {
        aF[ks][0] = A32[(arow + rq) * 28 + ks * 8 + c0];
        aF[ks][1] = A32[(arow + rq + 8) * 28 + ks * 8 + c0];
        aF[ks][2] = A32[(arow + rq) * 28 + ks * 8 + c0 + 4];
        aF[ks][3] = A32[(arow + rq + 8) * 28 + ks * 8 + c0 + 4];
    }
    for (int nt = 0; nt < 12; nt++) {
        uint32_t bF[3][2];
        int rowb = (nt * 8 + rq) * 28;
#pragma unroll
        for (int ks = 0; ks < 3; ks++) { bF[ks][0] = WB32[rowb + ks * 8 + c0]; bF[ks][1] = WB32[rowb + ks * 8 + c0 + 4]; }
        float d[4] = {0.f, 0.f, 0.f, 0.f};
        mma_bf16(d, aF[0], bF[0]);
        mma_bf16(d, aF[1], bF[1]);
        mma_bf16(d, aF[2], bF[2]);
#pragma unroll
        for (int e = 0; e < 2; e++) {
            int oc = ob + nt * 8 + 2 * c0 + e;
            float* base = (oc < 96) ? t1 : t2;
            int oo = (oc < 96) ? oc : oc - 96;
            size_t o0 = ((size_t)b * HID + oo) * HW + pp0;
            base[o0 + arow + rq]     = d[e];
            base[o0 + arow + rq + 8] = d[e + 2];
        }
    }
}

// ---------------- qkv 1x1 via warp MMA with inline LN ----------------
__global__ __launch_bounds__(256) void qkvm_k(const float* __restrict__ x,
        const float* __restrict__ n2w, const float* __restrict__ n2b,
        const __nv_bfloat16* __restrict__ wq, float* __restrict__ out)
{
    __shared__ uint32_t A32[128 * 28];
    __shared__ uint32_t WB32[72 * 28];
    __shared__ float SS1[256], SS2[256];
    __shared__ float sw1[CCH], sb1[CCH];
    int tid = threadIdx.x, wid = tid >> 5, lane = tid & 31;
    int c0 = lane & 3, rq = lane >> 2;
    int y = blockIdx.y;
    int ob = y * 72;
    int pb = blockIdx.x * 128;
    int b = pb >> 12, pp0 = pb & 4095;
    int px = tid & 127, half = tid >> 7;
    int pp = pp0 + px;

    if (tid < CCH) { sw1[tid] = n2w[tid]; sb1[tid] = n2b[tid]; }
    const float* xb = x + (size_t)b * CCH * HW + pp;
    float v[24];
    float s = 0.f, s2 = 0.f;
#pragma unroll
    for (int w = 0; w < 12; w++) {
        int c = (half * 12 + w) * 2;
        float a0 = xb[(size_t)c * HW], a1 = xb[(size_t)(c + 1) * HW];
        v[2 * w] = a0; v[2 * w + 1] = a1;
        s += a0 + a1; s2 += a0 * a0 + a1 * a1;
    }
    SS1[tid] = s; SS2[tid] = s2;
    const uint32_t* wbg = (const uint32_t*)wq;
    for (int i = tid; i < 72 * 24; i += 256) {
        int o = i / 24, w = i % 24;
        WB32[o * 28 + w] = wbg[(ob + o) * 24 + w];
    }
    __syncthreads();
    {
        float st  = SS1[px] + SS1[px + 128];
        float st2 = SS2[px] + SS2[px + 128];
        float mu = st * (1.f / CCH);
        float var = st2 * (1.f / CCH) - mu * mu;
        float r = rsqrtf(var + 1e-6f);
#pragma unroll
        for (int w = 0; w < 12; w++) {
            int c = (half * 12 + w) * 2;
            __nv_bfloat162 bv;
            bv.x = __float2bfloat16_rn(sw1[c] * (v[2 * w] - mu) * r + sb1[c]);
            bv.y = __float2bfloat16_rn(sw1[c + 1] * (v[2 * w + 1] - mu) * r + sb1[c + 1]);
            A32[px * 28 + half * 12 + w] = *(uint32_t*)&bv;
        }
    }
    __syncthreads();

    int arow = wid * 16;
    uint32_t aF[3][4];
#pragma unroll
    for (int ks = 0; ks < 3; ks++) {
        aF[ks][0] = A32[(arow + rq) * 28 + ks * 8 + c0];
        aF[ks][1] = A32[(arow + rq + 8) * 28 + ks * 8 + c0];
        aF[ks][2] = A32[(arow + rq) * 28 + ks * 8 + c0 + 4];
        aF[ks][3] = A32[(arow + rq + 8) * 28 + ks * 8 + c0 + 4];
    }
    for (int nt = 0; nt < 9; nt++) {
        uint32_t bF[3][2];
        int rowb = (nt * 8 + rq) * 28;
#pragma unroll
        for (int ks = 0; ks < 3; ks++) { bF[ks][0] = WB32[rowb + ks * 8 + c0]; bF[ks][1] = WB32[rowb + ks * 8 + c0 + 4]; }
        float d[4] = {0.f, 0.f, 0.f, 0.f};
        mma_bf16(d, aF[0], bF[0]);
        mma_bf16(d, aF[1], bF[1]);
        mma_bf16(d, aF[2], bF[2]);
#pragma unroll
        for (int e = 0; e < 2; e++) {
            int oc = ob + nt * 8 + 2 * c0 + e;
            size_t o0 = ((size_t)b * (3 * CCH) + oc) * HW + pp0;
            out[o0 + arow + rq]     = d[e];
            out[o0 + arow + rq + 8] = d[e + 2];
        }
    }
}

// ---------------- depthwise 3x3 for t1/t2 ----------------
__global__ void dw12_k(const float* __restrict__ t1, const float* __restrict__ kdw2,
                       const float* __restrict__ t2, const float* __restrict__ kc1b,
                       float* __restrict__ x1, float* __restrict__ uf)
{
    int gidx4 = (blockIdx.x * 256 + threadIdx.x);
    int p = (gidx4 * 4) & 4095;
    int plane = (gidx4 * 4) >> 12;
    int b = plane / 192, cg = plane % 192;
    const float* in; const float* wsrc; float* outp; int c;
    if (cg < 96) { in = t1; wsrc = kdw2; outp = x1; c = cg; }
    else         { in = t2; wsrc = kc1b; outp = uf; c = cg - 96; }
    int h = p >> 6, w0 = p & 63;
    const float* inp = in + ((size_t)b * 96 + c) * HW;
    const float* wc = wsrc + c * 9;
    float wk[9];
#pragma unroll
    for (int i = 0; i < 9; i++) wk[i] = __ldg(wc + i);
    float a[4] = {0.f, 0.f, 0.f, 0.f};
#pragma unroll
    for (int kh = 0; kh < 3; kh++) {
        int hh = h + kh - 1;
        if (hh < 0 || hh > 63) continue;
        const float* r = inp + hh * 64;
        float4 v14 = *(const float4*)(r + w0);
        float vm1 = (w0 > 0)  ? r[w0 - 1] : 0.f;
        float v5  = (w0 < 60) ? r[w0 + 4] : 0.f;
        float v[6] = {vm1, v14.x, v14.y, v14.z, v14.w, v5};
        float k0 = wk[kh * 3], k1 = wk[kh * 3 + 1], k2 = wk[kh * 3 + 2];
#pragma unroll
        for (int px = 0; px < 4; px++)
            a[px] += k0 * v[px] + k1 * v[px + 1] + k2 * v[px + 2];
    }
    ulonglong2 t; t.x = pk2(a[0], a[1]); t.y = pk2(a[2], a[3]);
    *(ulonglong2*)(outp + ((size_t)b * 96 + c) * HW + p) = t;
}

// ---------------- depthwise 3x3 for qkv ----------------
__global__ void dwq_k(const float* __restrict__ qkvt, const float* __restrict__ qkvw,
                      float* __restrict__ qkv)
{
    int gidx4 = (blockIdx.x * 256 + threadIdx.x);
    int p = (gidx4 * 4) & 4095;
    int plane = (gidx4 * 4) >> 12;
    int b = plane / 144, c = plane % 144;
    int h = p >> 6, w0 = p & 63;
    const float* inp = qkvt + ((size_t)b * 144 + c) * HW;
    const float* wc = qkvw + c * 9;
    float wk[9];
#pragma unroll
    for (int i = 0; i < 9; i++) wk[i] = __ldg(wc + i);
    float a[4] = {0.f, 0.f, 0.f, 0.f};
#pragma unroll
    for (int kh = 0; kh < 3; kh++) {
        int hh = h + kh - 1;
        if (hh < 0 || hh > 63) continue;
        const float* r = inp + hh * 64;
        float4 v14 = *(const float4*)(r + w0);
        float vm1 = (w0 > 0)  ? r[w0 - 1] : 0.f;
        float v5  = (w0 < 60) ? r[w0 + 4] : 0.f;
        float v[6] = {vm1, v14.x, v14.y, v14.z, v14.w, v5};
        float k0 = wk[kh * 3], k1 = wk[kh * 3 + 1], k2 = wk[kh * 3 + 2];
#pragma unroll
        for (int px = 0; px < 4; px++)
            a[px] += k0 * v[px] + k1 * v[px + 1] + k2 * v[px + 2];
    }
    ulonglong2 t; t.x = pk2(a[0], a[1]); t.y = pk2(a[2], a[3]);
    *(ulonglong2*)(qkv + ((size_t)b * 144 + c) * HW + p) = t;
}

// ---------------- attmix ----------------
__global__ __launch_bounds__(128) void attmix_k(const float* __restrict__ xn,
        const float* __restrict__ wA, const float* __restrict__ bA,
        const float* __restrict__ wB, const float* __restrict__ bB,
        const float* __restrict__ gam,
        const float* __restrict__ c211w, const float* __restrict__ c211b,
        float* __restrict__ att)
{
    __shared__ float swA[INTERC * 18], sbA[INTERC], swB[NSET * 12], sbB[NSET], sgam[NSET];
    __shared__ float sw3[NSET * CCH], sb3[NSET];
    __shared__ float scen[64 * 48];
    __shared__ float sav[64 * 24];
    int tid = threadIdx.x;
    for (int i = tid; i < INTERC * 18; i += 128) swA[i] = wA[i];
    if (tid < INTERC) sbA[tid] = bA[tid];
    for (int i = tid; i < NSET * 12; i += 128) swB[i] = wB[i];
    if (tid < NSET) { sbB[tid] = bB[tid]; sgam[tid] = gam[tid]; sb3[tid] = c211b[tid]; }
    for (int i = tid; i < NSET * CCH; i += 128) sw3[i] = c211w[i];
    __syncthreads();
    int px = tid & 63, half = tid >> 6;
    int pg = blockIdx.x * 64 + px;
    int b = pg >> 12, p = pg & 4095;
    int h = p >> 6, w = p & 63;
    const float* xb = xn + (size_t)b * CCH * HW;
#pragma unroll
    for (int oo = 0; oo < 12; oo++) {
        int o = half * 12 + oo;
        float acc = sbA[o];
#pragma unroll
        for (int t = 0; t < 2; t++) {
            int c = o * 2 + t;
            const float* ch = xb + (size_t)c * HW;
            float cen = 0.f;
#pragma unroll
            for (int kk = 0; kk < 9; kk++) {
                int hh = h + kk / 3 - 1, ww = w + kk % 3 - 1;
                if (hh >= 0 && hh < 64 && ww >= 0 && ww < 64) {
                    float vv = ch[hh * 64 + ww];
                    acc += swA[o * 18 + t * 9 + kk] * vv;
                    if (kk == 4) cen = vv;
                }
            }
            scen[px * 48 + c] = cen;
        }
        sav[px * 24 + o] = acc;
    }
    __syncthreads();
    float sg[12];
#pragma unroll
    for (int i = 0; i < 12; i++) sg[i] = sav[px * 24 + i] * sav[px * 24 + 12 + i];
#pragma unroll
    for (int nn = 0; nn < 16; nn++) {
        int n = half * 16 + nn;
        float s = sbB[n];
#pragma unroll
        for (int i = 0; i < 12; i++) s += swB[n * 12 + i] * sg[i];
        float c2 = sb3[n];
#pragma unroll
        for (int c = 0; c < 48; c++) c2 += sw3[n * 48 + c] * scen[px * 48 + c];
        att[((size_t)b * NSET + n) * HW + p] = sgam[n] * s + c2;
    }
}

// ================= KBA core via warp MMA, y-split x4 =================
#define KT_A 0
#define KT_B 18432
#define KT_P 41472
#define KT_TOTAL 61952

__global__ __launch_bounds__(256) void kba_mma_k(
        const float* __restrict__ uf, const float* __restrict__ att,
        const __nv_bfloat16* __restrict__ kwb, const float* __restrict__ ga1,
        const float* __restrict__ x1, float* __restrict__ mout)
{
    extern __shared__ __align__(16) char smraw[];
    uint32_t* A32 = (uint32_t*)(smraw + KT_A);
    uint32_t* B32 = (uint32_t*)(smraw + KT_B);
    float*    P   = (float*)(smraw + KT_P);

    int tid = threadIdx.x, wid = tid >> 5, lane = tid & 31;
    int c0 = lane & 3, rq = lane >> 2;
    int pb = blockIdx.x * 128;
    int b = pb >> 12, pp0 = pb & 4095;
    int g0 = blockIdx.y * 6;

    int px = tid & 127, half = tid >> 7;
    int pp = pp0 + px;
    int h = pp >> 6, w = pp & 63;

    {
        const float* attb = att + (size_t)b * NSET * HW + pp;
#pragma unroll
        for (int q = 0; q < 8; q++) {
            int n = (half * 8 + q) * 2;
            __nv_bfloat162 v;
            v.x = __float2bfloat16_rn(attb[(size_t)n * HW]);
            v.y = __float2bfloat16_rn(attb[(size_t)(n + 1) * HW]);
            A32[px * 36 + half * 8 + q] = *(uint32_t*)&v;
        }
    }
    int offs[9]; bool val[9];
#pragma unroll
    for (int kk = 0; kk < 9; kk++) {
        int dh = kk / 3 - 1, dw = kk % 3 - 1;
        int hh = h + dh, ww = w + dw;
        val[kk] = (hh >= 0 && hh < 64 && ww >= 0 && ww < 64);
        offs[kk] = hh * 64 + ww;
    }
    __syncthreads();

    int arow = 16 * wid + rq;
    uint32_t aF[2][4];
#pragma unroll
    for (int ks = 0; ks < 2; ks++) {
        int base = ks * 8;
        aF[ks][0] = A32[arow * 36 + base + c0];
        aF[ks][1] = A32[(arow + 8) * 36 + base + c0];
        aF[ks][2] = A32[arow * 36 + base + c0 + 4];
        aF[ks][3] = A32[(arow + 8) * 36 + base + c0 + 4];
    }

    for (int gi = 0; gi < 6; gi++) {
        int g = g0 + gi;
        __syncthreads();
        const uint32_t* kwb32 = (const uint32_t*)(kwb + (size_t)g * 160 * 32);
        for (int i = tid; i < 2560; i += 256) {
            int row = i >> 4, np = i & 15;
            B32[row * 36 + np] = kwb32[i];
        }
        const float* ufg = uf + ((size_t)b * HID + g * 4) * HW;
#pragma unroll
        for (int jj = 0; jj < 18; jj++) {
            int j = half * 18 + jj;
            int ci = j / 9, kk = j % 9;
            P[px * 40 + j] = val[kk] ? ufg[(size_t)ci * HW + offs[kk]] : 0.f;
        }
        __syncthreads();

#pragma unroll
        for (int cc = 0; cc < 4; cc++) {
            uint32_t bF[5][2][2];
            int nb = cc * 40;
#pragma unroll
            for (int t = 0; t < 5; t++) {
                int rowb = (nb + t * 8 + rq) * 36;
#pragma unroll
                for (int ks = 0; ks < 2; ks++) {
                    bF[t][ks][0] = B32[rowb + ks * 8 + c0];
                    bF[t][ks][1] = B32[rowb + ks * 8 + c0 + 4];
                }
            }
            float d[5][4];
#pragma unroll
            for (int t = 0; t < 5; t++) { d[t][0]=0.f; d[t][1]=0.f; d[t][2]=0.f; d[t][3]=0.f; }
#pragma unroll
            for (int t = 0; t < 5; t++) {
                mma_bf16(d[t], aF[0], bF[t][0]);
                mma_bf16(d[t], aF[1], bF[t][1]);
            }
            int rlo = 16 * wid + rq, rhi = rlo + 8;
            float s0 = 0.f, s1 = 0.f;
#pragma unroll
            for (int t = 0; t < 5; t++) {
                int j0 = t * 8 + 2 * c0, j1 = j0 + 1;
                float w00, w01, w10, w11;
                if (j0 < 36)      { w00 = P[rlo * 40 + j0]; w10 = P[rhi * 40 + j0]; }
                else if (j0 == 36){ w00 = 1.f; w10 = 1.f; }
                else              { w00 = 0.f; w10 = 0.f; }
                if (j1 < 36)      { w01 = P[rlo * 40 + j1]; w11 = P[rhi * 40 + j1]; }
                else              { w01 = 0.f; w11 = 0.f; }
                s0 += d[t][0] * w00 + d[t][1] * w01;
                s1 += d[t][2] * w10 + d[t][3] * w11;
            }
            s0 += __shfl_xor_sync(0xffffffffu, s0, 1);
            s0 += __shfl_xor_sync(0xffffffffu, s0, 2);
            s1 += __shfl_xor_sync(0xffffffffu, s1, 1);
            s1 += __shfl_xor_sync(0xffffffffu, s1, 2);
            if (c0 == 0) {
                int ch = g * 4 + cc;
                float ga = ga1[ch];
                float cen0 = P[rlo * 40 + cc * 9 + 4];
                float cen1 = P[rhi * 40 + cc * 9 + 4];
                float x2a = s0 * ga + cen0;
                float x2b = s1 * ga + cen1;
                size_t xlo = ((size_t)b * HID + ch) * HW + pp0 + rlo;
                size_t xhi = xlo + 8;
                float v0 = x1[xlo], v1 = x1[xhi];
                mout[xlo] = 0.5f * v0 * (1.f + erff(v0 * 0.70710678118654752f)) * x2a;
                mout[xhi] = 0.5f * v1 * (1.f + erff(v1 * 0.70710678118654752f)) * x2b;
            }
        }
    }
}

// ---------------- MDTA: fused norms + 6x6 attention + softmax ----------------
__global__ __launch_bounds__(256) void attn_k(const float* __restrict__ qkv,
        const float* __restrict__ temp, float* __restrict__ attn)
{
    int bh = blockIdx.x; int b = bh >> 3, h = bh & 7;
    int warp = threadIdx.x >> 5, lane = threadIdx.x & 31;
    __shared__ float S[36], NQ[6], NK[6];
    const float* qb = qkv + ((size_t)b * 3 * CCH + h * DHEAD) * HW;
    const float* kb = qkv + ((size_t)b * 3 * CCH + CCH + h * DHEAD) * HW;
    for (int pi = warp; pi < 48; pi += 8) {
        const float* pa; const float* pb;
        if (pi < 36)      { pa = qb + (size_t)(pi / 6) * HW; pb = kb + (size_t)(pi % 6) * HW; }
        else if (pi < 42) { pa = qb + (size_t)(pi - 36) * HW; pb = pa; }
        else              { pa = kb + (size_t)(pi - 42) * HW; pb = pa; }
        float s = 0.f;
        for (int t = lane * 4; t < HW; t += 128) {
            float4 va = *(const float4*)(pa + t);
            float4 vb = *(const float4*)(pb + t);
            s += va.x * vb.x + va.y * vb.y + va.z * vb.z + va.w * vb.w;
        }
#pragma unroll
        for (int off = 16; off; off >>= 1) s += __shfl_down_sync(0xffffffffu, s, off);
        if (lane == 0) {
            if (pi < 36) S[pi] = s;
            else if (pi < 42) NQ[pi - 36] = sqrtf(s);
            else NK[pi - 42] = sqrtf(s);
        }
    }
    __syncthreads();
    if (threadIdx.x < 6) {
        int i = threadIdx.x;
        float nq = fmaxf(NQ[i], 1e-12f);
        float tv = temp[h];
        float row[6]; float mx = -1e30f;
#pragma unroll
        for (int j = 0; j < 6; j++) {
            float nk = fmaxf(NK[j], 1e-12f);
            row[j] = tv * S[i * 6 + j] / (nq * nk);
            mx = fmaxf(mx, row[j]);
        }
        float sum = 0.f;
#pragma unroll
        for (int j = 0; j < 6; j++) { row[j] = expf(row[j] - mx); sum += row[j]; }
        float inv = 1.f / sum;
#pragma unroll
        for (int j = 0; j < 6; j++)
            attn[((size_t)(b * 8 + h) * 6 + i) * 6 + j] = row[j] * inv;
    }
}

// ---------------- MDTA: fused (attn @ v) + mproj ----------------
__global__ __launch_bounds__(128) void mdta_k(const float* __restrict__ qkv,
        const float* __restrict__ attn, const float* __restrict__ mproj,
        float* __restrict__ out)
{
    __shared__ float scoef[288];
    __shared__ u64 ws2[4 * CCH];
    int tid = threadIdx.x;
    int o0 = blockIdx.y * 4;
    int p4 = (blockIdx.x * 128 + tid) * 4;
    int b = p4 >> 12, pp = p4 & 4095;
    int bblk = (blockIdx.x * 512) >> 12;
    for (int i = tid; i < 288; i += 128) scoef[i] = attn[bblk * 288 + i];
    for (int i = tid; i < 4 * CCH; i += 128)
        ws2[i] = dup2(mproj[(o0 + i / CCH) * CCH + i % CCH]);
    __syncthreads();
    u64 acc[4][2];
#pragma unroll
    for (int o = 0; o < 4; o++) { acc[o][0] = 0ULL; acc[o][1] = 0ULL; }
    const float* vb = qkv + ((size_t)b * 3 * CCH + 2 * CCH) * HW + pp;
#pragma unroll
    for (int h = 0; h < 8; h++) {
        u64 v[6][2];
#pragma unroll
        for (int j = 0; j < 6; j++) {
            ulonglong2 t = *(const ulonglong2*)(vb + (size_t)(h * 6 + j) * HW);
            v[j][0] = t.x; v[j][1] = t.y;
        }
#pragma unroll
        for (int i = 0; i < 6; i++) {
            int c = h * 6 + i;
            u64 md0 = 0ULL, md1 = 0ULL;
#pragma unroll
            for (int j = 0; j < 6; j++) {
                u64 cf = dup2(scoef[c * 6 + j]);
                md0 = fma2_(cf, v[j][0], md0);
                md1 = fma2_(cf, v[j][1], md1);
            }
#pragma unroll
            for (int o = 0; o < 4; o++) {
                u64 wv = ws2[o * CCH + c];
                acc[o][0] = fma2_(wv, md0, acc[o][0]);
                acc[o][1] = fma2_(wv, md1, acc[o][1]);
            }
        }
    }
    float* outb = out + ((size_t)b * CCH + o0) * HW + pp;
#pragma unroll
    for (int o = 0; o < 4; o++) {
        ulonglong2 t; t.x = acc[o][0]; t.y = acc[o][1];
        *(ulonglong2*)(outb + (size_t)o * HW) = t;
    }
}

// ---------------- final via warp MMA ----------------
__global__ __launch_bounds__(256) void finalm_k(const float* __restrict__ x,
        const float* __restrict__ m, const float* __restrict__ mdta,
        const float* __restrict__ kproj, const float* __restrict__ gap,
        const float* __restrict__ ca1w, const float* __restrict__ ca1b,
        const float* __restrict__ ca2w, const float* __restrict__ ca2b,
        float* __restrict__ out)
{
    __shared__ uint32_t A32[128 * 52];
    __shared__ uint32_t WB32[48 * 52];
    __shared__ float sca1[48], sca2[48];
    int tid = threadIdx.x, wid = tid >> 5, lane = tid & 31;
    int c0 = lane & 3, rq = lane >> 2;
    int pb = blockIdx.x * 128;
    int b = pb >> 12, pp0 = pb & 4095;
    int px = tid & 127, half = tid >> 7;
    int pp = pp0 + px;

    const float* mb = m + (size_t)b * HID * HW + pp;
#pragma unroll
    for (int w = 0; w < 24; w++) {
        int c = (half * 24 + w) * 2;
        __nv_bfloat162 bv;
        bv.x = __float2bfloat16_rn(mb[(size_t)c * HW]);
        bv.y = __float2bfloat16_rn(mb[(size_t)(c + 1) * HW]);
        A32[px * 52 + half * 24 + w] = *(uint32_t*)&bv;
    }
    for (int i = tid; i < 48 * 48; i += 256) {
        int o = i / 48, w = i % 48;
        __nv_bfloat162 bv;
        bv.x = __float2bfloat16_rn(kproj[o * HID + 2 * w]);
        bv.y = __float2bfloat16_rn(kproj[o * HID + 2 * w + 1]);
        WB32[o * 52 + w] = *(uint32_t*)&bv;
    }
    if (tid < 48) {
        float s1 = ca1b[tid], s2 = ca2b[tid];
        for (int c = 0; c < CCH; c++) {
            float g = gap[b * CCH + c];
            s1 += ca1w[tid * CCH + c] * g;
            s2 += ca2w[tid * CCH + c] * g;
        }
        sca1[tid] = s1; sca2[tid] = s2;
    }
    __syncthreads();

    int arow = wid * 16;
    uint32_t aF[6][4];
#pragma unroll
    for (int ks = 0; ks < 6; ks++) {
        aF[ks][0] = A32[(arow + rq) * 52 + ks * 8 + c0];
        aF[ks][1] = A32[(arow + rq + 8) * 52 + ks * 8 + c0];
        aF[ks][2] = A32[(arow + rq) * 52 + ks * 8 + c0 + 4];
        aF[ks][3] = A32[(arow + rq + 8) * 52 + ks * 8 + c0 + 4];
    }
#pragma unroll
    for (int nt = 0; nt < 6; nt++) {
        uint32_t bF[6][2];
        int rowb = (nt * 8 + rq) * 52;
#pragma unroll
        for (int ks = 0; ks < 6; ks++) { bF[ks][0] = WB32[rowb + ks * 8 + c0]; bF[ks][1] = WB32[rowb + ks * 8 + c0 + 4]; }
        float d[4] = {0.f, 0.f, 0.f, 0.f};
#pragma unroll
        for (int ks = 0; ks < 6; ks++) mma_bf16(d, aF[ks], bF[ks]);
#pragma unroll
        for (int e = 0; e < 2; e++) {
            int oc = nt * 8 + 2 * c0 + e;
            float a1 = sca1[oc], a2 = sca2[oc];
            size_t o0 = ((size_t)b * CCH + oc) * HW + pp0;
            size_t i0 = o0 + arow + rq, i1 = i0 + 8;
            out[i0] = x[i0] + a1 * d[e]     + a2 * mdta[i0];
            out[i1] = x[i1] + a1 * d[e + 2] + a2 * mdta[i1];
        }
    }
}

// ---------------- host launcher ----------------
extern "C" void kernel_launch(void* const* d_in, const int* in_sizes, int n_in,
                              void* d_out, int out_size)
{
    const float* x       = (const float*)d_in[0];
    const float* n1w     = (const float*)d_in[1];
    const float* n1b     = (const float*)d_in[2];
    const float* n2w     = (const float*)d_in[3];
    const float* n2b     = (const float*)d_in[4];
    const float* kdw1    = (const float*)d_in[5];
    const float* kdw2    = (const float*)d_in[6];
    const float* kc1a    = (const float*)d_in[7];
    const float* kc1b    = (const float*)d_in[8];
    const float* kproj   = (const float*)d_in[9];
    const float* c2a_w   = (const float*)d_in[10];
    const float* c2a_b   = (const float*)d_in[11];
    const float* c2b_w   = (const float*)d_in[12];
    const float* c2b_b   = (const float*)d_in[13];
    const float* c211_w  = (const float*)d_in[14];
    const float* c211_b  = (const float*)d_in[15];
    const float* kw      = (const float*)d_in[16];
    const float* kb      = (const float*)d_in[17];
    const float* attg    = (const float*)d_in[18];
    const float* ga1     = (const float*)d_in[19];
    const float* temp    = (const float*)d_in[20];
    const float* qkv_w   = (const float*)d_in[21];
    const float* qkv_dww = (const float*)d_in[22];
    const float* mproj_w = (const float*)d_in[23];
    const float* ca1_w   = (const float*)d_in[24];
    const float* ca1_b   = (const float*)d_in[25];
    const float* ca2_w   = (const float*)d_in[26];
    const float* ca2_b   = (const float*)d_in[27];
    float* out = (float*)d_out;

    float* S = nullptr;
    cudaGetSymbolAddress((void**)&S, g_scratch);
    float* xn   = S + OFF_XN;
    float* t1   = S + OFF_T1;
    float* t2   = S + OFF_T2;
    float* x1   = S + OFF_X1;
    float* uf   = S + OFF_UF;
    float* att  = S + OFF_ATT;
    float* qkvt = S + OFF_QKVT;
    float* qkv  = S + OFF_QKV;
    float* m    = S + OFF_M;
    float* gap  = S + OFF_GAP;
    float* attn = S + OFF_ATTN;
    __nv_bfloat16* kwb = (__nv_bfloat16*)(S + OFF_KWB);
    __nv_bfloat16* wb  = (__nv_bfloat16*)(S + OFF_WB);
    __nv_bfloat16* wq  = (__nv_bfloat16*)(S + OFF_WQ);
    float* mdta = qkvt;                     // reuse

    const int PIX = BATCH * HW;             // 16384
    const int XB4 = PIX / 512;              // 32

    static cudaStream_t sB = nullptr, sC = nullptr;
    static cudaEvent_t evRoot = nullptr, evP = nullptr, evB = nullptr, evC = nullptr;
    if (sB == nullptr) {
        cudaStreamCreateWithFlags(&sB, cudaStreamNonBlocking);
        cudaStreamCreateWithFlags(&sC, cudaStreamNonBlocking);
        cudaEventCreateWithFlags(&evRoot, cudaEventDisableTiming);
        cudaEventCreateWithFlags(&evP, cudaEventDisableTiming);
        cudaEventCreateWithFlags(&evB, cudaEventDisableTiming);
        cudaEventCreateWithFlags(&evC, cudaEventDisableTiming);
        cudaFuncSetAttribute(kba_mma_k, cudaFuncAttributeMaxDynamicSharedMemorySize, KT_TOTAL);
    }

    cudaEventRecord(evRoot, 0);
    cudaStreamWaitEvent(sC, evRoot, 0);
    cudaStreamWaitEvent(sB, evRoot, 0);

    // ---- stream C: ln(xn) -> attmix ----
    ln_k<<<PIX / 64, 256, 0, sC>>>(x, n1w, n1b, xn);
    attmix_k<<<PIX / 64, 128, 0, sC>>>(xn, c2a_w, c2a_b, c2b_w, c2b_b, attg,
                                       c211_w, c211_b, att);
    cudaEventRecord(evC, sC);

    // ---- main: prep+gap ----
    const int PREP_N = 24 * 160 * 32 + 192 * 48 + 144 * 48;
    prepgap_k<<<GAPB + (PREP_N + 255) / 256, 256>>>(x, kw, kb, kdw1, kc1a, qkv_w,
                                                    gap, kwb, wb, wq);
    cudaEventRecord(evP, 0);

    // ---- stream B: MDTA chain ----
    cudaStreamWaitEvent(sB, evP, 0);
    qkvm_k<<<dim3(PIX / 128, 2), 256, 0, sB>>>(x, n2w, n2b, wq, qkvt);
    dwq_k<<<BATCH * 144 * HW / 1024, 256, 0, sB>>>(qkvt, qkv_dww, qkv);
    attn_k<<<BATCH * HEADS, 256, 0, sB>>>(qkv, temp, attn);
    mdta_k<<<dim3(XB4, 12), 128, 0, sB>>>(qkv, attn, mproj_w, mdta);
    cudaEventRecord(evB, sB);

    // ---- main: KBA critical path ----
    fused3m_k<<<dim3(PIX / 128, 2), 256>>>(x, n1w, n1b, wb, t1, t2);
    dw12_k<<<BATCH * 192 * HW / 1024, 256>>>(t1, kdw2, t2, kc1b, x1, uf);
    cudaStreamWaitEvent(0, evC, 0);
    kba_mma_k<<<dim3(PIX / 128, 4), 256, KT_TOTAL>>>(uf, att, kwb, ga1, x1, m);
    cudaStreamWaitEvent(0, evB, 0);
    finalm_k<<<PIX / 128, 256>>>(x, m, mdta, kproj, gap,
                                 ca1_w, ca1_b, ca2_w, ca2_b, out);
}